// round 15
// baseline (speedup 1.0000x reference)
#include <cuda_runtime.h>
#include <cuda_bf16.h>
#include <math.h>
#include <stdint.h>

#define BS     4
#define NQ     10000
#define NV     13294
#define EMBED  256
#define HEADS  8
#define DH     32

typedef __nv_bfloat16 bf16;

// scratch (no allocations allowed)
__device__ bf16  g_vah[BS * NV * EMBED];          // value input, bf16
__device__ bf16  g_qh[BS * NQ * EMBED];           // query input, bf16
__device__ bf16  g_wvh[EMBED * 256];              // weights [k][n], bf16
__device__ bf16  g_woffh[EMBED * 256];
__device__ bf16  g_wwh[EMBED * 128];
__device__ bf16  g_woh[EMBED * 256];
__device__ bf16  g_vh[BS * HEADS * NV * DH];      // projected value, bf16, head-major
__device__ float g_proj_off[BS * NQ * 256];
__device__ float g_proj_w[BS * NQ * 128];
__device__ bf16  g_msdah[BS * NQ * 256];          // sampled output, bf16

// ---------------------------------------------------------------------------
// fp32 -> bf16 conversion, all 6 tensors in one launch (pure bandwidth)
// ---------------------------------------------------------------------------
__device__ __forceinline__ void cvt_store4(const float4 x, bf16* d) {
    __nv_bfloat162 h0 = __floats2bfloat162_rn(x.x, x.y);
    __nv_bfloat162 h1 = __floats2bfloat162_rn(x.z, x.w);
    uint32_t u0, u1; memcpy(&u0, &h0, 4); memcpy(&u1, &h1, 4);
    *(uint2*)d = make_uint2(u0, u1);
}

__global__ void cvt_all_kernel(const float* __restrict__ q, const float* __restrict__ v,
                               const float* __restrict__ w0, const float* __restrict__ w1,
                               const float* __restrict__ w2, const float* __restrict__ w3)
{
    const int nq = BS * NQ * EMBED / 4;
    const int nv = BS * NV * EMBED / 4;
    const int n0 = 16384, n1 = 16384, n2 = 8192, n3 = 16384;
    const int total = nq + nv + n0 + n1 + n2 + n3;
    int i = blockIdx.x * blockDim.x + threadIdx.x;
    int stride = gridDim.x * blockDim.x;
    for (; i < total; i += stride) {
        int j = i;
        if (j < nq) { cvt_store4(((const float4*)q)[j], g_qh + j * 4); continue; }
        j -= nq;
        if (j < nv) { cvt_store4(((const float4*)v)[j], g_vah + j * 4); continue; }
        j -= nv;
        if (j < n0) { cvt_store4(((const float4*)w0)[j], g_wvh + j * 4); continue; }
        j -= n0;
        if (j < n1) { cvt_store4(((const float4*)w1)[j], g_woffh + j * 4); continue; }
        j -= n1;
        if (j < n2) { cvt_store4(((const float4*)w2)[j], g_wwh + j * 4); continue; }
        j -= n2;
        cvt_store4(((const float4*)w3)[j], g_woh + j * 4);
    }
}

// ---------------------------------------------------------------------------
// Warp-autonomous bf16 mma.sync GEMM. CTA tile 128x128, K=256.
// B (256x128) preloaded to smem ONCE (stride 136); one __syncthreads total.
// Warp w owns output rows wid*16..+15: its A chunks (16x16) flow through a
// private 5-stage cp.async pipeline gated only by per-thread wait + syncwarp.
// Per k-chunk: 1 LDSM(A x4) + 8 LDSM(B x4.trans) + 16 HMMA m16n8k16.
// mode: 0 = fp32 out, 1 = head-major bf16 value out, 2 = fp32 out + residual.
// ---------------------------------------------------------------------------
struct GemmDesc {
    const bf16* A; const bf16* B; const float* bias; const float* R;
    void* C; int M, N, mblk, nblk, mode;
};

#define GK       256
#define NKIT     16
#define NSTA     5
#define B_STRIDE 136                       // halves per B smem row
#define B_BYTES  (GK * B_STRIDE * 2)       // 69632
#define A_STAGE_B 768                      // 16 rows * 24 halves * 2
#define A_WARP_B (NSTA * A_STAGE_B)        // 3840
#define GSMEM_TOTAL (B_BYTES + 8 * A_WARP_B)   // 100352

__device__ __forceinline__ void cp_async16(uint32_t dst, const void* src, bool full) {
    int sz = full ? 16 : 0;
    asm volatile("cp.async.ca.shared.global [%0], [%1], 16, %2;"
                 :: "r"(dst), "l"(src), "r"(sz));
}

__global__ void __launch_bounds__(256, 2)
gemm_wa(GemmDesc d0, GemmDesc d1, GemmDesc d2)
{
    extern __shared__ __align__(16) bf16 smem[];
    const uint32_t smem_u = (uint32_t)__cvta_generic_to_shared(smem);

    GemmDesc d = d0;
    int bid = blockIdx.x;
    if (bid >= d0.mblk * d0.nblk) {
        bid -= d0.mblk * d0.nblk;
        if (bid < d1.mblk * d1.nblk) d = d1;
        else { bid -= d1.mblk * d1.nblk; d = d2; }
    }
    const int bm = (bid / d.nblk) * 128;
    const int bn = (bid % d.nblk) * 128;

    const int tid  = threadIdx.x;
    const int lane = tid & 31;
    const int wid  = tid >> 5;
    const int lq   = lane >> 2, lr = lane & 3;

    // ---- B preload: 256 rows x 128 cols bf16 -> smem stride 136 (1 group) ----
    {
        const bf16* bsrc = d.B + bn;
#pragma unroll
        for (int c = 0; c < 16; c++) {
            const int cc = tid + c * 256;       // 4096 16B chunks
            const int k = cc >> 4, nc = cc & 15;
            cp_async16(smem_u + (k * B_STRIDE + nc * 8) * 2,
                       bsrc + (size_t)k * d.N + nc * 8, true);
        }
        asm volatile("cp.async.commit_group;");
    }

    // ---- A pipeline setup (per warp) ----
    const int a_row = bm + wid * 16 + (lane >> 1);
    const bool a_ok = a_row < d.M;
    const bf16* a_src = d.A + (size_t)(a_ok ? a_row : 0) * GK + (lane & 1) * 8;
    const uint32_t a_wbase = smem_u + B_BYTES + wid * A_WARP_B;
    const uint32_t a_dst   = a_wbase + (lane >> 1) * 48 + (lane & 1) * 16;

#pragma unroll
    for (int s = 0; s < NSTA - 1; s++) {       // stages 0..3 -> chunks 0..3
        cp_async16(a_dst + s * A_STAGE_B, a_src + s * 16, a_ok);
        asm volatile("cp.async.commit_group;");
    }

    // drain B (leave the NSTA-1 A groups pending), then the one block sync
    asm volatile("cp.async.wait_group %0;" :: "n"(NSTA - 1));
    __syncthreads();

    float acc[16][4] = {};   // [n8-tile][creg]

    // ---- barrier-free mainloop over 16 k-chunks ----
#pragma unroll
    for (int i = 0; i < NKIT; i++) {
        const int pf = i + NSTA - 1;
        if (pf < NKIT)
            cp_async16(a_dst + (pf % NSTA) * A_STAGE_B, a_src + pf * 16, a_ok);
        asm volatile("cp.async.commit_group;");
        asm volatile("cp.async.wait_group %0;" :: "n"(NSTA - 2));
        __syncwarp();

        uint32_t af[4];
        {
            uint32_t addr = a_wbase + (i % NSTA) * A_STAGE_B +
                            ((lane & 15) * 24 + (lane >> 4) * 8) * 2;
            asm volatile("ldmatrix.sync.aligned.m8n8.x4.shared.b16 {%0,%1,%2,%3}, [%4];"
                         : "=r"(af[0]), "=r"(af[1]), "=r"(af[2]), "=r"(af[3]) : "r"(addr));
        }
        uint32_t bfr[8][4];
#pragma unroll
        for (int in2 = 0; in2 < 8; in2++) {
            uint32_t addr = smem_u +
                (((i * 16 + (lane & 15)) * B_STRIDE) + in2 * 16 + (lane >> 4) * 8) * 2;
            asm volatile("ldmatrix.sync.aligned.m8n8.x4.trans.shared.b16 {%0,%1,%2,%3}, [%4];"
                         : "=r"(bfr[in2][0]), "=r"(bfr[in2][1]),
                           "=r"(bfr[in2][2]), "=r"(bfr[in2][3]) : "r"(addr));
        }
#pragma unroll
        for (int in = 0; in < 16; in++) {
            asm volatile(
                "mma.sync.aligned.m16n8k16.row.col.f32.bf16.bf16.f32 "
                "{%0,%1,%2,%3}, {%4,%5,%6,%7}, {%8,%9}, {%0,%1,%2,%3};"
                : "+f"(acc[in][0]), "+f"(acc[in][1]), "+f"(acc[in][2]), "+f"(acc[in][3])
                : "r"(af[0]), "r"(af[1]), "r"(af[2]), "r"(af[3]),
                  "r"(bfr[in >> 1][(in & 1) * 2]), "r"(bfr[in >> 1][(in & 1) * 2 + 1]));
        }
    }

    // ---- epilogue (per warp, rows wid*16 + lq / +8) ----
#pragma unroll
    for (int half = 0; half < 2; half++) {
        const int m = bm + wid * 16 + lq + half * 8;
        if (m >= d.M) continue;
        int vb = 0, vpos = 0;
        if (d.mode == 1) { vb = m / NV; vpos = m - vb * NV; }
#pragma unroll
        for (int in = 0; in < 16; in++) {
            const int n = bn + in * 8 + lr * 2;
            float o0 = acc[in][half * 2 + 0] + __ldg(d.bias + n);
            float o1 = acc[in][half * 2 + 1] + __ldg(d.bias + n + 1);
            if (d.mode == 2) {
                const float2 r = *(const float2*)(d.R + (size_t)m * d.N + n);
                o0 += r.x; o1 += r.y;
            }
            if (d.mode == 1) {
                const int hh = n >> 5, c = n & 31;
                size_t dst = (((size_t)vb * HEADS + hh) * NV + vpos) * DH + c;
                *(__nv_bfloat162*)((bf16*)d.C + dst) = __floats2bfloat162_rn(o0, o1);
            } else {
                *(float2*)((float*)d.C + (size_t)m * d.N + n) = make_float2(o0, o1);
            }
        }
    }
}

// ---------------------------------------------------------------------------
// Deformable sampling (unchanged from the 263us kernel): 2 queries/block,
// head-major value, lane owns one (row, pos, chquad); deferred shfl reduction.
// ---------------------------------------------------------------------------
__global__ void msda_kernel(const float* __restrict__ refp)  // [bs, nq, 4, 2]
{
    const int bq0 = blockIdx.x * 2;
    const int tid = threadIdx.x;

    __shared__ uint2 s_rec[2][512];   // [q][slot*4 + pos*2 + row] = {rowbase_u32, w}

    {
        const int q  = tid >> 7;
        const int s  = tid & 127;
        const int bq = bq0 + q;
        const int b  = bq / NQ;
        const int h  = s >> 4, lp = s & 15, l = lp >> 2;

        float logit = g_proj_w[(size_t)bq * 128 + s];
        float mx = logit;
#pragma unroll
        for (int o = 8; o; o >>= 1) mx = fmaxf(mx, __shfl_xor_sync(0xffffffffu, mx, o));
        float e = __expf(logit - mx);
        float ssum = e;
#pragma unroll
        for (int o = 8; o; o >>= 1) ssum += __shfl_xor_sync(0xffffffffu, ssum, o);
        const float a = e / ssum;

        const int HWs[4]    = {100, 50, 25, 13};
        const int starts[4] = {0, 10000, 12500, 13125};
        const int W = HWs[l], H = W, st = starts[l];

        const float2 off = *(const float2*)(g_proj_off + (size_t)bq * 256 + s * 2);
        const float2 ref = *(const float2*)(refp + (size_t)bq * 8 + l * 2);
        const float x = ref.x * (float)W + off.x - 0.5f;
        const float y = ref.y * (float)H + off.y - 0.5f;
        const float x0f = floorf(x), y0f = floorf(y);
        const float fx = x - x0f, fy = y - y0f;
        const int x0 = (int)x0f, y0 = (int)y0f;
        const int x1 = x0 + 1,  y1 = y0 + 1;

        const bool vx0 = (x0 >= 0) & (x0 < W), vx1 = (x1 >= 0) & (x1 < W);
        const bool vy0 = (y0 >= 0) & (y0 < H), vy1 = (y1 >= 0) & (y1 < H);
        const int cx0 = min(max(x0, 0), W - 1), cx1 = min(max(x1, 0), W - 1);
        const int cy0 = min(max(y0, 0), H - 1), cy1 = min(max(y1, 0), H - 1);
        const int px  = min(max(x0, 0), W - 2);
        const int s0  = cx0 - px, s1 = cx1 - px;

        const float wx0 = vx0 ? (1.f - fx) : 0.f;
        const float wx1 = vx1 ? fx : 0.f;
        const float wy0 = vy0 ? (1.f - fy) * a : 0.f;
        const float wy1 = vy1 ? fy * a : 0.f;
        const float wh0 = (s0 == 0 ? wx0 : 0.f) + (s1 == 0 ? wx1 : 0.f);
        const float wh1 = (s0 == 1 ? wx0 : 0.f) + (s1 == 1 ? wx1 : 0.f);

        const int plane = ((b * HEADS + h) * NV + st);
        const uint32_t i0 = (uint32_t)(plane + cy0 * W + px) * 16u;
        const uint32_t i1 = (uint32_t)(plane + cy1 * W + px) * 16u;
        const int base = s * 4;
        s_rec[q][base + 0] = make_uint2(i0, (uint32_t)__float_as_int(wh0 * wy0));
        s_rec[q][base + 1] = make_uint2(i1, (uint32_t)__float_as_int(wh0 * wy1));
        s_rec[q][base + 2] = make_uint2(i0, (uint32_t)__float_as_int(wh1 * wy0));
        s_rec[q][base + 3] = make_uint2(i1, (uint32_t)__float_as_int(wh1 * wy1));
    }
    __syncthreads();

    const int h    = tid >> 5, lane = tid & 31;
    const int row  = lane >> 4;
    const int pos  = (lane >> 3) & 1;
    const int cq   = lane & 7;
    const int laneoff = pos * 16 + cq * 2;
    const int recsel  = pos * 2 + row;
    const uint32_t* vp = (const uint32_t*)g_vh;

#pragma unroll
    for (int qi = 0; qi < 2; qi++) {
        const int bq = bq0 + qi;
        float a0 = 0.f, a1 = 0.f, a2 = 0.f, a3 = 0.f;
#pragma unroll
        for (int lp = 0; lp < 16; lp++) {
            const uint2 rec = s_rec[qi][(h * 16 + lp) * 4 + recsel];
            const float w = __int_as_float((int)rec.y);
            const uint2 dv = *(const uint2*)(vp + rec.x + laneoff);
            float2 v0 = __bfloat1622float2(*(const __nv_bfloat162*)&dv.x);
            float2 v1 = __bfloat1622float2(*(const __nv_bfloat162*)&dv.y);
            a0 += w * v0.x; a1 += w * v0.y;
            a2 += w * v1.x; a3 += w * v1.y;
        }
        a0 += __shfl_xor_sync(0xffffffffu, a0, 8);
        a1 += __shfl_xor_sync(0xffffffffu, a1, 8);
        a2 += __shfl_xor_sync(0xffffffffu, a2, 8);
        a3 += __shfl_xor_sync(0xffffffffu, a3, 8);
        a0 += __shfl_xor_sync(0xffffffffu, a0, 16);
        a1 += __shfl_xor_sync(0xffffffffu, a1, 16);
        a2 += __shfl_xor_sync(0xffffffffu, a2, 16);
        a3 += __shfl_xor_sync(0xffffffffu, a3, 16);
        if (lane < 8) {
            __nv_bfloat162 p0 = __floats2bfloat162_rn(a0, a1);
            __nv_bfloat162 p1 = __floats2bfloat162_rn(a2, a3);
            uint32_t u0, u1; memcpy(&u0, &p0, 4); memcpy(&u1, &p1, 4);
            ((uint2*)g_msdah)[(size_t)bq * 64 + h * 8 + cq] = make_uint2(u0, u1);
        }
    }
}

// ---------------------------------------------------------------------------
extern "C" void kernel_launch(void* const* d_in, const int* in_sizes, int n_in,
                              void* d_out, int out_size)
{
    const float* query = (const float*)d_in[0];
    const float* value = (const float*)d_in[1];
    const float* refp  = (const float*)d_in[2];
    const float* Wv    = (const float*)d_in[4];
    const float* bv    = (const float*)d_in[5];
    const float* Woff  = (const float*)d_in[6];
    const float* boff  = (const float*)d_in[7];
    const float* Ww    = (const float*)d_in[8];
    const float* bw    = (const float*)d_in[9];
    const float* Wo    = (const float*)d_in[10];
    const float* bo    = (const float*)d_in[11];
    float* out = (float*)d_out;

    bf16 *p_vah, *p_qh, *p_wvh, *p_woffh, *p_wwh, *p_woh, *p_vh, *p_msdah;
    float *p_poff, *p_pw;
    cudaGetSymbolAddress((void**)&p_vah,   g_vah);
    cudaGetSymbolAddress((void**)&p_qh,    g_qh);
    cudaGetSymbolAddress((void**)&p_wvh,   g_wvh);
    cudaGetSymbolAddress((void**)&p_woffh, g_woffh);
    cudaGetSymbolAddress((void**)&p_wwh,   g_wwh);
    cudaGetSymbolAddress((void**)&p_woh,   g_woh);
    cudaGetSymbolAddress((void**)&p_vh,    g_vh);
    cudaGetSymbolAddress((void**)&p_poff,  g_proj_off);
    cudaGetSymbolAddress((void**)&p_pw,    g_proj_w);
    cudaGetSymbolAddress((void**)&p_msdah, g_msdah);

    cudaFuncSetAttribute(gemm_wa, cudaFuncAttributeMaxDynamicSharedMemorySize, GSMEM_TOTAL);

    const int Mv = BS * NV;   // 53176
    const int Mq = BS * NQ;   // 40000

    // 0) fp32 -> bf16 conversions (one launch)
    cvt_all_kernel<<<1184, 256>>>(query, value, Wv, Woff, Ww, Wo);

    // 1-3) fused: value proj (head-major bf16) + offsets + logits
    GemmDesc dv   = {p_vah, p_wvh,   bv,   nullptr, p_vh,   Mv, 256, (Mv + 127) / 128, 2, 1};
    GemmDesc doff = {p_qh,  p_woffh, boff, nullptr, p_poff, Mq, 256, (Mq + 127) / 128, 2, 0};
    GemmDesc dw   = {p_qh,  p_wwh,   bw,   nullptr, p_pw,   Mq, 128, (Mq + 127) / 128, 1, 0};
    int nblocks = dv.mblk * dv.nblk + doff.mblk * doff.nblk + dw.mblk * dw.nblk;
    gemm_wa<<<nblocks, 256, GSMEM_TOTAL>>>(dv, doff, dw);

    // 4) deformable sampling
    msda_kernel<<<Mq / 2, 256>>>(refp);

    // 5) out = msda @ Wo + bo + query
    GemmDesc dout = {p_msdah, p_woh, bo, query, out, Mq, 256, (Mq + 127) / 128, 2, 2};
    GemmDesc dnull = {nullptr, nullptr, nullptr, nullptr, nullptr, 0, 0, 0, 0, 0};
    gemm_wa<<<dout.mblk * dout.nblk, 256, GSMEM_TOTAL>>>(dout, dnull, dnull);
}